// round 8
// baseline (speedup 1.0000x reference)
#include <cuda_runtime.h>
#include <math.h>
#include <stdint.h>

typedef unsigned long long ull;

#define S_LEN   128
#define BATCH   1024
#define D0      300
#define D1      74
#define D2      35
#define HID     40
#define EMB     256
#define MM      3
#define RED_DIM 115            // 2*HID + D2
#define LSTM_IN 121            // RED_DIM + 2*MM
#define KTOT    377            // LSTM_IN + EMB
#define KPAD    384            // 12 chunks * 32
#define NCH     12
#define NROWS   (S_LEN*BATCH)
#define NBLK    128
#define THR     512

// ---- fragment-major smem layout (float offsets) ----
// W_hi frag: [ntile 8][chunk 12][ktile 4][lane 32][slot 2] = 24576
// W_lo frag: 2 bufs of [ntile 8][ktile 4][lane 32][slot 2] = 2048 each
// A hi frag: 2 bufs of [rtile 8][ktile 4][lane 32][slot 4] = 4096 each
#define OFF_WHIF 0                                // 24576
#define OFF_WLOF (OFF_WHIF + 24576)               // 4096
#define OFF_AHI  (OFF_WLOF + 2 * 2048)            // 8192
#define OFF_ALO  (OFF_AHI + 2 * 4096)             // 8192
#define OFF_PREV (OFF_ALO + 2 * 4096)             // 768
#define OFF_BIAS (OFF_PREV + 128 * 6)             // 64
#define SMEM_F   (OFF_BIAS + 64)                  // 45888 floats = 183552 B
// epilogue stage (128*65 = 8320 floats) aliases [OFF_AHI, OFF_AHI+16384)

// ---------------- device scratch ----------------
__device__ float g_reduced[(size_t)NROWS * RED_DIM];
__device__ float g_h[2][BATCH * EMB];
__device__ float g_wlo[1024 * KPAD];
__device__ unsigned g_counts[8];

__device__ __forceinline__ float sigm(float x) { return 1.f / (1.f + expf(-x)); }
__device__ __forceinline__ float to_tf32(float x) {
    float r; asm("cvt.rna.tf32.f32 %0, %1;" : "=f"(r) : "f"(x)); return r;
}
__device__ __forceinline__ void mma8(float* d, float4 a, float2 b) {
    asm volatile(
        "mma.sync.aligned.m16n8k8.row.col.f32.tf32.tf32.f32 "
        "{%0,%1,%2,%3}, {%4,%5,%6,%7}, {%8,%9}, {%0,%1,%2,%3};"
        : "+f"(d[0]), "+f"(d[1]), "+f"(d[2]), "+f"(d[3])
        : "r"(__float_as_uint(a.x)), "r"(__float_as_uint(a.y)),
          "r"(__float_as_uint(a.z)), "r"(__float_as_uint(a.w)),
          "r"(__float_as_uint(b.x)), "r"(__float_as_uint(b.y)));
}

// -------------------- init --------------------
__global__ void init_kernel() {
    int i = blockIdx.x * blockDim.x + threadIdx.x;
    if (i < 8) g_counts[i] = 0u;
    if (i < BATCH * EMB) { g_h[0][i] = 0.f; g_h[1][i] = 0.f; }
}

// -------------------- W low-part split --------------------
__global__ void wsplit_kernel(const float* __restrict__ W_ih, const float* __restrict__ W_hh) {
    int idx = blockIdx.x * blockDim.x + threadIdx.x;
    if (idx >= 1024 * KPAD) return;
    int grow = idx / KPAD, k = idx % KPAD;
    float w;
    if (k < LSTM_IN)     w = W_ih[grow * LSTM_IN + k];
    else if (k < KTOT)   w = W_hh[grow * EMB + (k - LSTM_IN)];
    else                 w = 0.f;
    g_wlo[idx] = to_tf32(w - to_tf32(w));
}

// -------------------- phase 1 (proven) --------------------
__global__ void phase1_kernel(const float* __restrict__ x0, const float* __restrict__ x1,
                              const float* __restrict__ x2,
                              const float* __restrict__ W0, const float* __restrict__ b0p,
                              const float* __restrict__ W1, const float* __restrict__ b1p) {
    extern __shared__ float sm[];
    float* sW0 = sm;
    float* sW1 = sm + 40 * 300;
    const int tid = threadIdx.x;

    for (int i = tid; i < 40 * 300; i += 320) sW0[i] = W0[i];
    for (int i = tid; i < 40 * 76; i += 320) {
        int r = i / 76, c = i % 76;
        sW1[i] = (c < D1) ? W1[r * D1 + c] : 0.f;
    }
    __syncthreads();

    const int r0 = blockIdx.x * 32;
    const int o  = tid % 40;
    const int rb = (tid / 40) * 4;
    {
        const float bv = b0p[o];
        float acc[4] = {bv, bv, bv, bv};
        const float4* wv = (const float4*)(sW0 + o * D0);
        const float4* xr[4];
#pragma unroll
        for (int j = 0; j < 4; j++) xr[j] = (const float4*)(x0 + (size_t)(r0 + rb + j) * D0);
#pragma unroll 5
        for (int k4 = 0; k4 < 75; k4++) {
            float4 w = wv[k4];
#pragma unroll
            for (int j = 0; j < 4; j++) {
                float4 a = __ldg(&xr[j][k4]);
                acc[j] += w.x * a.x + w.y * a.y + w.z * a.z + w.w * a.w;
            }
        }
#pragma unroll
        for (int j = 0; j < 4; j++)
            g_reduced[(size_t)(r0 + rb + j) * RED_DIM + o] = acc[j];
    }
    {
        const float bv = b1p[o];
        float acc[4] = {bv, bv, bv, bv};
        const float2* wv = (const float2*)(sW1 + o * 76);
        const float2* xr[4];
#pragma unroll
        for (int j = 0; j < 4; j++) xr[j] = (const float2*)(x1 + (size_t)(r0 + rb + j) * D1);
#pragma unroll 4
        for (int k2 = 0; k2 < 37; k2++) {
            float2 w = wv[k2];
#pragma unroll
            for (int j = 0; j < 4; j++) {
                float2 a = __ldg(&xr[j][k2]);
                acc[j] += w.x * a.x + w.y * a.y;
            }
        }
#pragma unroll
        for (int j = 0; j < 4; j++)
            g_reduced[(size_t)(r0 + rb + j) * RED_DIM + HID + o] = acc[j];
    }
    for (int i = tid; i < 32 * D2; i += 320) {
        int r = i / D2, c = i % D2;
        g_reduced[(size_t)(r0 + r) * RED_DIM + 2 * HID + c] = x2[(size_t)(r0 + r) * D2 + c];
    }
}

// -------------------- persistent mma.sync kernel, fragment-major smem --------------------
// grid 128 (bt 0..7 x et 0..15), block 512 = 16 warps (4 row x 4 col).
// Warp (wr,wc): rows wr*32+{0..31} (rtiles wr*2, wr*2+1), cols wc*16+{0..15}
// (ntiles wc*2, wc*2+1). All fragments pre-permuted in smem:
//   A: one LDS.128 per (mt, hi/lo, kk); W: one LDS.64 per (nt, hi/lo, kk).
__global__ void __launch_bounds__(THR, 1) persist_kernel(
    const float* __restrict__ W_ih, const float* __restrict__ W_hh,
    const float* __restrict__ b_ih, const float* __restrict__ b_hh,
    const float* __restrict__ W_dec, const float* __restrict__ b_dec,
    const float* __restrict__ gum, float* __restrict__ out) {

    extern __shared__ float smf[];

    const int tid  = threadIdx.x;
    const int lane = tid & 31;
    const int warp = tid >> 5;                 // 0..15
    const int wr   = warp & 3;
    const int wc   = warp >> 2;
    const int bt   = blockIdx.x >> 4;
    const int et   = blockIdx.x & 15;
    const int bb0  = bt * 128;
    const int e0   = et * 16;

    float* sWhiF = smf + OFF_WHIF;
    float* sWloF = smf + OFF_WLOF;
    float* sAhi  = smf + OFF_AHI;
    float* sAlo  = smf + OFF_ALO;
    float* sPrev = smf + OFF_PREV;
    float* sBias = smf + OFF_BIAS;
    float* stg   = smf + OFF_AHI;              // epilogue stage aliases A buffers

    // ---- one-time: resident W_hi in fragment layout; bias ----
    for (int i = tid; i < 64 * KPAD; i += THR) {
        int col = i / KPAD, k = i % KPAD;      // col = gate*16+ei local (0..63)
        int grow = (col >> 4) * EMB + e0 + (col & 15);
        float w;
        if (k < LSTM_IN)     w = W_ih[grow * LSTM_IN + k];
        else if (k < KTOT)   w = W_hh[grow * EMB + (k - LSTM_IN)];
        else                 w = 0.f;
        int ntg = col >> 3, n = col & 7;
        int c = k >> 5, kt = (k >> 3) & 3, kc = k & 7;
        int addr = (((ntg * NCH + c) * 4 + kt) * 32 + n * 4 + (kc & 3)) * 2 + (kc >= 4 ? 1 : 0);
        sWhiF[addr] = to_tf32(w);
    }
    if (tid < 64) {
        int gg = tid >> 4, ei = tid & 15;
        sBias[tid] = b_ih[gg * EMB + e0 + ei] + b_hh[gg * EMB + e0 + ei];
    }
    __syncthreads();

    float creg[4];
#pragma unroll
    for (int j = 0; j < 4; j++) creg[j] = 0.f;

    // ---- builder mappings ----
    // A: thread owns row pr (0..127), 8 ks at pko (one k-tile)
    const int pr  = tid >> 2;
    const int pko = (tid & 3) * 8;
    const int pb  = bb0 + pr;
    const int a_tile_base = ((pr >> 4) * 4 + (pko >> 3)) * 128
                          + ((pr & 7) & 7) * 16 + ((pr >> 3) & 1);
    // W_lo: thread owns col pwc (0..63), 4 ks at pwk (half of one k-tile)
    const int pwc = tid >> 3;
    const int pwk = (tid & 7) * 4;
    const int pwrow = (pwc >> 4) * EMB + e0 + (pwc & 15);
    const int w_frag_base = ((pwc >> 3) * 4 + (pwk >> 3)) * 64
                          + (pwc & 7) * 8 + ((pwk & 4) ? 1 : 0);

    volatile unsigned* bar = &g_counts[bt];

    for (int t = 0; t <= S_LEN; t++) {
        const float* __restrict__ hprev = g_h[t & 1];
        const float* __restrict__ red_t = g_reduced + (size_t)t * BATCH * RED_DIM;

        float pf[8], pw[4];
        if (t < S_LEN) {
            // chunk 0: k<32 < RED_DIM
#pragma unroll
            for (int x = 0; x < 8; x++)
                pf[x] = __ldg(&red_t[(size_t)pb * RED_DIM + pko + x]);
            float4 v = *(const float4*)(g_wlo + (size_t)pwrow * KPAD + pwk);
            pw[0] = v.x; pw[1] = v.y; pw[2] = v.z; pw[3] = v.w;
        }

        // ---------------- decoder prologue for step t-1 ----------------
        if (t == 0) {
            for (int i = tid; i < 128 * 6; i += THR) sPrev[i] = 0.f;
        } else {
            const int tprev = t - 1;
            const bool wrt = (et == 0);
            for (int r2 = 0; r2 < 8; r2++) {
                const int rloc = warp * 8 + r2;
                const int b = bb0 + rloc;
                float hv[8];
#pragma unroll
                for (int i = 0; i < 8; i++) hv[i] = __ldcg(&hprev[b * EMB + lane + 32 * i]);
                float lg[6];
#pragma unroll
                for (int mo = 0; mo < 6; mo++) {
                    float p = 0.f;
#pragma unroll
                    for (int i = 0; i < 8; i++)
                        p += hv[i] * __ldg(&W_dec[mo * EMB + lane + 32 * i]);
                    p += __shfl_xor_sync(0xffffffffu, p, 16);
                    p += __shfl_xor_sync(0xffffffffu, p, 8);
                    p += __shfl_xor_sync(0xffffffffu, p, 4);
                    p += __shfl_xor_sync(0xffffffffu, p, 2);
                    p += __shfl_xor_sync(0xffffffffu, p, 1);
                    p += __ldg(&b_dec[mo]);
                    lg[mo] = p;
                    if (lane == mo) sPrev[rloc * 6 + mo] = p;
                }
                if (wrt && lane < MM) {
                    const int m = lane;
                    size_t gbase = ((size_t)tprev * (MM * BATCH) + m * BATCH + b) * 2;
                    float u0 = gum[gbase], u1 = gum[gbase + 1];
                    float gg0 = -logf(-logf(u0));
                    float gg1 = -logf(-logf(u1));
                    float l0 = lg[2 * m], l1 = lg[2 * m + 1];
                    out[((size_t)tprev * MM + m) * BATCH + b] =
                        (l1 + gg1 > l0 + gg0) ? 1.f : 0.f;
                    size_t lbase = (size_t)S_LEN * MM * BATCH +
                                   (((size_t)tprev * MM + m) * BATCH + b) * 2;
                    out[lbase]     = l0;
                    out[lbase + 1] = l1;
                }
            }
        }
        if (t == S_LEN) break;

        // ---- stage chunk 0 into buf0 (fragment layout); prefetch chunk 1 ----
        {
            float* dAh = sAhi;
            float* dAl = sAlo;
#pragma unroll
            for (int x = 0; x < 8; x++) {
                float v  = pf[x];
                float hi = to_tf32(v);
                int addr = a_tile_base + (x & 3) * 4 + ((x >= 4) ? 2 : 0);
                dAh[addr] = hi;
                dAl[addr] = to_tf32(v - hi);
            }
#pragma unroll
            for (int x = 0; x < 4; x++) sWloF[w_frag_base + x * 2] = pw[x];
            const int kb = 32 + pko;
#pragma unroll
            for (int x = 0; x < 8; x++)
                pf[x] = __ldg(&red_t[(size_t)pb * RED_DIM + kb + x]);
            float4 v = *(const float4*)(g_wlo + (size_t)pwrow * KPAD + 32 + pwk);
            pw[0] = v.x; pw[1] = v.y; pw[2] = v.z; pw[3] = v.w;
        }
        __syncthreads();

        float accP[2][2][4], accQ[2][2][4];
#pragma unroll
        for (int mt = 0; mt < 2; mt++)
#pragma unroll
            for (int nt = 0; nt < 2; nt++)
#pragma unroll
                for (int x = 0; x < 4; x++) { accP[mt][nt][x] = 0.f; accQ[mt][nt][x] = 0.f; }

        // ---------------- chunk loop (1 sync/chunk) ----------------
        for (int c = 0; c < NCH; c++) {
            const int buf  = c & 1;
            const int nbuf = buf ^ 1;

            // stage chunk c+1 into nbuf; prefetch c+2
            if (c + 1 < NCH) {
                float* dAh = sAhi + nbuf * 4096;
                float* dAl = sAlo + nbuf * 4096;
                float* dWl = sWloF + nbuf * 2048;
#pragma unroll
                for (int x = 0; x < 8; x++) {
                    float v  = pf[x];
                    float hi = to_tf32(v);
                    int addr = a_tile_base + (x & 3) * 4 + ((x >= 4) ? 2 : 0);
                    dAh[addr] = hi;
                    dAl[addr] = to_tf32(v - hi);
                }
#pragma unroll
                for (int x = 0; x < 4; x++) dWl[w_frag_base + x * 2] = pw[x];
                if (c + 2 < NCH) {
                    const int kb = (c + 2) * 32 + pko;
#pragma unroll
                    for (int x = 0; x < 8; x++) {
                        int kg = kb + x;
                        float v;
                        if (kg < RED_DIM)       v = __ldg(&red_t[(size_t)pb * RED_DIM + kg]);
                        else if (kg < LSTM_IN)  v = sPrev[pr * 6 + (kg - RED_DIM)];
                        else if (kg < KTOT)     v = __ldcg(&hprev[pb * EMB + (kg - LSTM_IN)]);
                        else                    v = 0.f;
                        pf[x] = v;
                    }
                    float4 v = *(const float4*)(g_wlo + (size_t)pwrow * KPAD +
                                                (c + 2) * 32 + pwk);
                    pw[0] = v.x; pw[1] = v.y; pw[2] = v.z; pw[3] = v.w;
                }
            }

            // ---- MMA on buf: fragment loads are LDS.128 / LDS.64 ----
            const float4* fAh = (const float4*)(sAhi + buf * 4096);
            const float4* fAl = (const float4*)(sAlo + buf * 4096);
            const float2* fWh = (const float2*)sWhiF;
            const float2* fWl = (const float2*)(sWloF + buf * 2048);
#pragma unroll
            for (int kk = 0; kk < 4; kk++) {
                float4 ah[2], al[2];
#pragma unroll
                for (int mt = 0; mt < 2; mt++) {
                    const int rt = wr * 2 + mt;
                    ah[mt] = fAh[(rt * 4 + kk) * 32 + lane];
                    al[mt] = fAl[(rt * 4 + kk) * 32 + lane];
                }
#pragma unroll
                for (int nt = 0; nt < 2; nt++) {
                    const int ntg = wc * 2 + nt;
                    float2 bh = fWh[((ntg * NCH + c) * 4 + kk) * 32 + lane];
                    float2 bl = fWl[(ntg * 4 + kk) * 32 + lane];
#pragma unroll
                    for (int mt = 0; mt < 2; mt++) {
                        mma8(accP[mt][nt], ah[mt], bh);
                        mma8(accQ[mt][nt], ah[mt], bl);
                        mma8(accQ[mt][nt], al[mt], bh);
                        mma8(accP[mt][nt], al[mt], bl);
                    }
                }
            }
            __syncthreads();
        }

        // ---------------- epilogue: accs -> stage -> LSTM cell ----------------
        {
            const int g = lane >> 2, q = lane & 3;
#pragma unroll
            for (int mt = 0; mt < 2; mt++)
#pragma unroll
                for (int nt = 0; nt < 2; nt++) {
                    const int r0m  = wr * 32 + mt * 16 + g;
                    const int col0 = wc * 16 + nt * 8 + 2 * q;
                    stg[r0m * 65 + col0]           = accP[mt][nt][0] + accQ[mt][nt][0];
                    stg[r0m * 65 + col0 + 1]       = accP[mt][nt][1] + accQ[mt][nt][1];
                    stg[(r0m + 8) * 65 + col0]     = accP[mt][nt][2] + accQ[mt][nt][2];
                    stg[(r0m + 8) * 65 + col0 + 1] = accP[mt][nt][3] + accQ[mt][nt][3];
                }
        }
        __syncthreads();
        {
            const int r = tid >> 2, ei0 = (tid & 3) * 4;
            const int b = bb0 + r;
            const int nb = (t + 1) & 1;
            float hrow[4];
#pragma unroll
            for (int x = 0; x < 4; x++) {
                int ei = ei0 + x;
                float iv = stg[r * 65 + 0  + ei] + sBias[0 * 16 + ei];
                float fv = stg[r * 65 + 16 + ei] + sBias[1 * 16 + ei];
                float gv = stg[r * 65 + 32 + ei] + sBias[2 * 16 + ei];
                float ov = stg[r * 65 + 48 + ei] + sBias[3 * 16 + ei];
                float i_ = sigm(iv), f_ = sigm(fv), g_ = tanhf(gv), o_ = sigm(ov);
                float cn = f_ * creg[x] + i_ * g_;
                creg[x] = cn;
                hrow[x] = o_ * tanhf(cn);
            }
            *(float4*)(&g_h[nb][b * EMB + e0 + ei0]) =
                make_float4(hrow[0], hrow[1], hrow[2], hrow[3]);
        }

        // ---------------- bt-group barrier (16 blocks) ----------------
        __syncthreads();
        if (tid == 0) {
            __threadfence();
            atomicAdd((unsigned*)bar, 1u);
            const unsigned tgt = (unsigned)(t + 1) * 16u;
            while (*bar < tgt) __nanosleep(32);
        }
        __syncthreads();
    }
}

// -------------------- launch --------------------
extern "C" void kernel_launch(void* const* d_in, const int* in_sizes, int n_in,
                              void* d_out, int out_size) {
    const float* x0    = (const float*)d_in[0];
    const float* x1    = (const float*)d_in[1];
    const float* x2    = (const float*)d_in[2];
    // d_in[3] = x_lens (unused)
    const float* gum   = (const float*)d_in[4];
    const float* W0    = (const float*)d_in[5];
    const float* b0    = (const float*)d_in[6];
    const float* W1    = (const float*)d_in[7];
    const float* b1    = (const float*)d_in[8];
    const float* W_ih  = (const float*)d_in[9];
    const float* W_hh  = (const float*)d_in[10];
    const float* b_ih  = (const float*)d_in[11];
    const float* b_hh  = (const float*)d_in[12];
    const float* W_dec = (const float*)d_in[13];
    const float* b_dec = (const float*)d_in[14];
    float* out = (float*)d_out;

    init_kernel<<<(BATCH * EMB + 255) / 256, 256>>>();
    wsplit_kernel<<<(1024 * KPAD + 255) / 256, 256>>>(W_ih, W_hh);

    size_t smem1 = (size_t)(40 * 300 + 40 * 76) * sizeof(float);
    cudaFuncSetAttribute(phase1_kernel,
                         cudaFuncAttributeMaxDynamicSharedMemorySize, (int)smem1);
    phase1_kernel<<<NROWS / 32, 320, smem1>>>(x0, x1, x2, W0, b0, W1, b1);

    size_t smemP = (size_t)SMEM_F * sizeof(float);   // 183552 B
    cudaFuncSetAttribute(persist_kernel,
                         cudaFuncAttributeMaxDynamicSharedMemorySize, (int)smemP);
    persist_kernel<<<NBLK, THR, smemP>>>(W_ih, W_hh, b_ih, b_hh,
                                         W_dec, b_dec, gum, out);
}

// round 9
// speedup vs baseline: 1.5718x; 1.5718x over previous
#include <cuda_runtime.h>
#include <math.h>
#include <stdint.h>

typedef unsigned long long ull;

#define S_LEN   128
#define BATCH   1024
#define D0      300
#define D1      74
#define D2      35
#define HID     40
#define EMB     256
#define MM      3
#define RED_DIM 115            // 2*HID + D2
#define LSTM_IN 121            // RED_DIM + 2*MM
#define KTOT    377            // LSTM_IN + EMB
#define KPAD    384            // 12 chunks * 32
#define NCH     12
#define NROWS   (S_LEN*BATCH)
#define NBLK    128
#define THR     512

#define W_STR   388            // resident W_hi stride (388%32==4 -> conflict-free frags)
#define A_STR   36             // A / W_lo chunk stride (36%32==4)

// ---- smem layout (float offsets) ----
#define OFF_WHI  0                               // 64*388      = 24832
#define OFF_WLO  (OFF_WHI + 64 * W_STR)          // 2*64*36     = 4608
#define OFF_AHI  (OFF_WLO + 2 * 64 * A_STR)      // 2*128*36    = 9216
#define OFF_ALO  (OFF_AHI + 2 * 128 * A_STR)     // 2*128*36    = 9216
#define OFF_PREV (OFF_ALO + 2 * 128 * A_STR)     // 128*6       = 768
#define OFF_BIAS (OFF_PREV + 128 * 6)            // 64
#define SMEM_F   (OFF_BIAS + 64)                 // 48704 floats = 194816 B
// epilogue stage (128*65=8320 floats) aliases the A buffers at OFF_AHI

// ---------------- device scratch ----------------
__device__ float g_reduced[(size_t)NROWS * RED_DIM];
__device__ float g_h[2][BATCH * EMB];
__device__ float g_wlo[1024 * KPAD];
__device__ unsigned g_counts[8];

__device__ __forceinline__ float sigm(float x) { return 1.f / (1.f + expf(-x)); }
__device__ __forceinline__ float to_tf32(float x) {
    float r; asm("cvt.rna.tf32.f32 %0, %1;" : "=f"(r) : "f"(x)); return r;
}
__device__ __forceinline__ void mma8(float* d,
        uint32_t a0, uint32_t a1, uint32_t a2, uint32_t a3,
        uint32_t b0, uint32_t b1) {
    asm volatile(
        "mma.sync.aligned.m16n8k8.row.col.f32.tf32.tf32.f32 "
        "{%0,%1,%2,%3}, {%4,%5,%6,%7}, {%8,%9}, {%0,%1,%2,%3};"
        : "+f"(d[0]), "+f"(d[1]), "+f"(d[2]), "+f"(d[3])
        : "r"(a0), "r"(a1), "r"(a2), "r"(a3), "r"(b0), "r"(b1));
}

// -------------------- init --------------------
__global__ void init_kernel() {
    int i = blockIdx.x * blockDim.x + threadIdx.x;
    if (i < 8) g_counts[i] = 0u;
    if (i < BATCH * EMB) { g_h[0][i] = 0.f; g_h[1][i] = 0.f; }
}

// -------------------- W low-part split --------------------
__global__ void wsplit_kernel(const float* __restrict__ W_ih, const float* __restrict__ W_hh) {
    int idx = blockIdx.x * blockDim.x + threadIdx.x;
    if (idx >= 1024 * KPAD) return;
    int grow = idx / KPAD, k = idx % KPAD;
    float w;
    if (k < LSTM_IN)     w = W_ih[grow * LSTM_IN + k];
    else if (k < KTOT)   w = W_hh[grow * EMB + (k - LSTM_IN)];
    else                 w = 0.f;
    g_wlo[idx] = to_tf32(w - to_tf32(w));
}

// -------------------- phase 1 (proven) --------------------
__global__ void phase1_kernel(const float* __restrict__ x0, const float* __restrict__ x1,
                              const float* __restrict__ x2,
                              const float* __restrict__ W0, const float* __restrict__ b0p,
                              const float* __restrict__ W1, const float* __restrict__ b1p) {
    extern __shared__ float sm[];
    float* sW0 = sm;
    float* sW1 = sm + 40 * 300;
    const int tid = threadIdx.x;

    for (int i = tid; i < 40 * 300; i += 320) sW0[i] = W0[i];
    for (int i = tid; i < 40 * 76; i += 320) {
        int r = i / 76, c = i % 76;
        sW1[i] = (c < D1) ? W1[r * D1 + c] : 0.f;
    }
    __syncthreads();

    const int r0 = blockIdx.x * 32;
    const int o  = tid % 40;
    const int rb = (tid / 40) * 4;
    {
        const float bv = b0p[o];
        float acc[4] = {bv, bv, bv, bv};
        const float4* wv = (const float4*)(sW0 + o * D0);
        const float4* xr[4];
#pragma unroll
        for (int j = 0; j < 4; j++) xr[j] = (const float4*)(x0 + (size_t)(r0 + rb + j) * D0);
#pragma unroll 5
        for (int k4 = 0; k4 < 75; k4++) {
            float4 w = wv[k4];
#pragma unroll
            for (int j = 0; j < 4; j++) {
                float4 a = __ldg(&xr[j][k4]);
                acc[j] += w.x * a.x + w.y * a.y + w.z * a.z + w.w * a.w;
            }
        }
#pragma unroll
        for (int j = 0; j < 4; j++)
            g_reduced[(size_t)(r0 + rb + j) * RED_DIM + o] = acc[j];
    }
    {
        const float bv = b1p[o];
        float acc[4] = {bv, bv, bv, bv};
        const float2* wv = (const float2*)(sW1 + o * 76);
        const float2* xr[4];
#pragma unroll
        for (int j = 0; j < 4; j++) xr[j] = (const float2*)(x1 + (size_t)(r0 + rb + j) * D1);
#pragma unroll 4
        for (int k2 = 0; k2 < 37; k2++) {
            float2 w = wv[k2];
#pragma unroll
            for (int j = 0; j < 4; j++) {
                float2 a = __ldg(&xr[j][k2]);
                acc[j] += w.x * a.x + w.y * a.y;
            }
        }
#pragma unroll
        for (int j = 0; j < 4; j++)
            g_reduced[(size_t)(r0 + rb + j) * RED_DIM + HID + o] = acc[j];
    }
    for (int i = tid; i < 32 * D2; i += 320) {
        int r = i / D2, c = i % D2;
        g_reduced[(size_t)(r0 + r) * RED_DIM + 2 * HID + c] = x2[(size_t)(r0 + r) * D2 + c];
    }
}

// -------------------- persistent mma.sync recurrent kernel (16 warps) --------------------
// R7 structure (proven 5804us) + 3-term split (hh, hl, lh) + vectorized builder stores.
__global__ void __launch_bounds__(THR, 1) persist_kernel(
    const float* __restrict__ W_ih, const float* __restrict__ W_hh,
    const float* __restrict__ b_ih, const float* __restrict__ b_hh,
    const float* __restrict__ W_dec, const float* __restrict__ b_dec,
    const float* __restrict__ gum, float* __restrict__ out) {

    extern __shared__ float smf[];

    const int tid  = threadIdx.x;
    const int lane = tid & 31;
    const int warp = tid >> 5;                 // 0..15
    const int wr   = warp & 3;                 // warp row (32 rows)
    const int wc   = warp >> 2;                // warp col (16 cols)
    const int bt   = blockIdx.x >> 4;
    const int et   = blockIdx.x & 15;
    const int bb0  = bt * 128;
    const int e0   = et * 16;

    const int g    = lane >> 2;
    const int q    = lane & 3;

    float* sWhi  = smf + OFF_WHI;
    float* sWlo  = smf + OFF_WLO;              // 2 bufs of 64*A_STR
    float* sAhi  = smf + OFF_AHI;              // 2 bufs of 128*A_STR
    float* sAlo  = smf + OFF_ALO;
    float* sPrev = smf + OFF_PREV;
    float* sBias = smf + OFF_BIAS;
    float* stg   = smf + OFF_AHI;              // epilogue stage aliases A buffers

    // ---- one-time: resident W_hi (tf32-rounded), bias ----
    for (int i = tid; i < 64 * KPAD; i += THR) {
        int col = i / KPAD, k = i % KPAD;
        int grow = (col >> 4) * EMB + e0 + (col & 15);
        float w;
        if (k < LSTM_IN)     w = W_ih[grow * LSTM_IN + k];
        else if (k < KTOT)   w = W_hh[grow * EMB + (k - LSTM_IN)];
        else                 w = 0.f;
        sWhi[col * W_STR + k] = to_tf32(w);
    }
    if (tid < 64) {
        int gg = tid >> 4, ei = tid & 15;
        sBias[tid] = b_ih[gg * EMB + e0 + ei] + b_hh[gg * EMB + e0 + ei];
    }
    __syncthreads();

    float creg[4];
#pragma unroll
    for (int j = 0; j < 4; j++) creg[j] = 0.f;

    // fill mappings
    const int pr  = tid >> 2;                  // A row 0..127
    const int pko = (tid & 3) * 8;             // A k-offset 0,8,16,24
    const int pb  = bb0 + pr;
    const int pwc = tid >> 3;                  // W col 0..63
    const int pwk = (tid & 7) * 4;             // W k-offset 0..28
    const int pwrow = (pwc >> 4) * EMB + e0 + (pwc & 15);

    volatile unsigned* bar = &g_counts[bt];

    for (int t = 0; t <= S_LEN; t++) {
        const float* __restrict__ hprev = g_h[t & 1];
        const float* __restrict__ red_t = g_reduced + (size_t)t * BATCH * RED_DIM;

        float pf[8], pw[4];
        if (t < S_LEN) {
#pragma unroll
            for (int x = 0; x < 8; x++)
                pf[x] = __ldg(&red_t[(size_t)pb * RED_DIM + pko + x]);
            float4 v = *(const float4*)(g_wlo + (size_t)pwrow * KPAD + pwk);
            pw[0] = v.x; pw[1] = v.y; pw[2] = v.z; pw[3] = v.w;
        }

        // ---------------- decoder prologue for step t-1 ----------------
        if (t == 0) {
            for (int i = tid; i < 128 * 6; i += THR) sPrev[i] = 0.f;
        } else {
            const int tprev = t - 1;
            const bool wrt = (et == 0);
            for (int r2 = 0; r2 < 8; r2++) {
                const int rloc = warp * 8 + r2;
                const int b = bb0 + rloc;
                float hv[8];
#pragma unroll
                for (int i = 0; i < 8; i++) hv[i] = __ldcg(&hprev[b * EMB + lane + 32 * i]);
                float lg[6];
#pragma unroll
                for (int mo = 0; mo < 6; mo++) {
                    float p = 0.f;
#pragma unroll
                    for (int i = 0; i < 8; i++)
                        p += hv[i] * __ldg(&W_dec[mo * EMB + lane + 32 * i]);
                    p += __shfl_xor_sync(0xffffffffu, p, 16);
                    p += __shfl_xor_sync(0xffffffffu, p, 8);
                    p += __shfl_xor_sync(0xffffffffu, p, 4);
                    p += __shfl_xor_sync(0xffffffffu, p, 2);
                    p += __shfl_xor_sync(0xffffffffu, p, 1);
                    p += __ldg(&b_dec[mo]);
                    lg[mo] = p;
                    if (lane == mo) sPrev[rloc * 6 + mo] = p;
                }
                if (wrt && lane < MM) {
                    const int m = lane;
                    size_t gbase = ((size_t)tprev * (MM * BATCH) + m * BATCH + b) * 2;
                    float u0 = gum[gbase], u1 = gum[gbase + 1];
                    float gg0 = -logf(-logf(u0));
                    float gg1 = -logf(-logf(u1));
                    float l0 = lg[2 * m], l1 = lg[2 * m + 1];
                    out[((size_t)tprev * MM + m) * BATCH + b] =
                        (l1 + gg1 > l0 + gg0) ? 1.f : 0.f;
                    size_t lbase = (size_t)S_LEN * MM * BATCH +
                                   (((size_t)tprev * MM + m) * BATCH + b) * 2;
                    out[lbase]     = l0;
                    out[lbase + 1] = l1;
                }
            }
        }
        if (t == S_LEN) break;

        // ---- stage chunk 0 into buf0 (vector stores); prefetch chunk 1 ----
        {
            float4 vh0, vh1, vl0, vl1;
            float* ph0 = (float*)&vh0; float* pl0 = (float*)&vl0;
            float* ph1 = (float*)&vh1; float* pl1 = (float*)&vl1;
#pragma unroll
            for (int x = 0; x < 4; x++) {
                float hi = to_tf32(pf[x]);
                ph0[x] = hi; pl0[x] = to_tf32(pf[x] - hi);
                float hi2 = to_tf32(pf[x + 4]);
                ph1[x] = hi2; pl1[x] = to_tf32(pf[x + 4] - hi2);
            }
            *(float4*)(sAhi + pr * A_STR + pko)     = vh0;
            *(float4*)(sAhi + pr * A_STR + pko + 4) = vh1;
            *(float4*)(sAlo + pr * A_STR + pko)     = vl0;
            *(float4*)(sAlo + pr * A_STR + pko + 4) = vl1;
            *(float4*)(sWlo + pwc * A_STR + pwk) = make_float4(pw[0], pw[1], pw[2], pw[3]);

            const int kb = 32 + pko;
#pragma unroll
            for (int x = 0; x < 8; x++)
                pf[x] = __ldg(&red_t[(size_t)pb * RED_DIM + kb + x]);
            float4 v = *(const float4*)(g_wlo + (size_t)pwrow * KPAD + 32 + pwk);
            pw[0] = v.x; pw[1] = v.y; pw[2] = v.z; pw[3] = v.w;
        }
        __syncthreads();

        float accP[2][2][4], accQ[2][2][4];
#pragma unroll
        for (int mt = 0; mt < 2; mt++)
#pragma unroll
            for (int nt = 0; nt < 2; nt++)
#pragma unroll
                for (int x = 0; x < 4; x++) { accP[mt][nt][x] = 0.f; accQ[mt][nt][x] = 0.f; }

        // ---------------- chunk loop (1 sync/chunk) ----------------
        for (int c = 0; c < NCH; c++) {
            const int buf  = c & 1;
            const int nbuf = buf ^ 1;

            // stage prefetched chunk c+1 into nbuf (vector stores); prefetch c+2
            if (c + 1 < NCH) {
                float* dAh = sAhi + nbuf * 128 * A_STR;
                float* dAl = sAlo + nbuf * 128 * A_STR;
                float* dWl = sWlo + nbuf * 64 * A_STR;
                float4 vh0, vh1, vl0, vl1;
                float* ph0 = (float*)&vh0; float* pl0 = (float*)&vl0;
                float* ph1 = (float*)&vh1; float* pl1 = (float*)&vl1;
#pragma unroll
                for (int x = 0; x < 4; x++) {
                    float hi = to_tf32(pf[x]);
                    ph0[x] = hi; pl0[x] = to_tf32(pf[x] - hi);
                    float hi2 = to_tf32(pf[x + 4]);
                    ph1[x] = hi2; pl1[x] = to_tf32(pf[x + 4] - hi2);
                }
                *(float4*)(dAh + pr * A_STR + pko)     = vh0;
                *(float4*)(dAh + pr * A_STR + pko + 4) = vh1;
                *(float4*)(dAl + pr * A_STR + pko)     = vl0;
                *(float4*)(dAl + pr * A_STR + pko + 4) = vl1;
                *(float4*)(dWl + pwc * A_STR + pwk) = make_float4(pw[0], pw[1], pw[2], pw[3]);

                if (c + 2 < NCH) {
                    const int kb = (c + 2) * 32 + pko;
#pragma unroll
                    for (int x = 0; x < 8; x++) {
                        int kg = kb + x;
                        float v;
                        if (kg < RED_DIM)       v = __ldg(&red_t[(size_t)pb * RED_DIM + kg]);
                        else if (kg < LSTM_IN)  v = sPrev[pr * 6 + (kg - RED_DIM)];
                        else if (kg < KTOT)     v = __ldcg(&hprev[pb * EMB + (kg - LSTM_IN)]);
                        else                    v = 0.f;
                        pf[x] = v;
                    }
                    float4 v = *(const float4*)(g_wlo + (size_t)pwrow * KPAD +
                                                (c + 2) * 32 + pwk);
                    pw[0] = v.x; pw[1] = v.y; pw[2] = v.z; pw[3] = v.w;
                }
            }

            // MMA on buf: 3-term split (hh -> accP, hl + lh -> accQ)
            const uint32_t* uAh = (const uint32_t*)(sAhi + buf * 128 * A_STR);
            const uint32_t* uAl = (const uint32_t*)(sAlo + buf * 128 * A_STR);
            const uint32_t* uWh = (const uint32_t*)sWhi;
            const uint32_t* uWl = (const uint32_t*)(sWlo + buf * 64 * A_STR);
#pragma unroll
            for (int kk = 0; kk < 4; kk++) {
                const int k0 = kk * 8;
                uint32_t ah[2][4], al[2][4];
#pragma unroll
                for (int mt = 0; mt < 2; mt++) {
                    const int r0m = wr * 32 + mt * 16 + g;
                    ah[mt][0] = uAh[r0m * A_STR + k0 + q];
                    ah[mt][1] = uAh[(r0m + 8) * A_STR + k0 + q];
                    ah[mt][2] = uAh[r0m * A_STR + k0 + q + 4];
                    ah[mt][3] = uAh[(r0m + 8) * A_STR + k0 + q + 4];
                    al[mt][0] = uAl[r0m * A_STR + k0 + q];
                    al[mt][1] = uAl[(r0m + 8) * A_STR + k0 + q];
                    al[mt][2] = uAl[r0m * A_STR + k0 + q + 4];
                    al[mt][3] = uAl[(r0m + 8) * A_STR + k0 + q + 4];
                }
#pragma unroll
                for (int nt = 0; nt < 2; nt++) {
                    const int col = wc * 16 + nt * 8 + g;
                    uint32_t bh0 = uWh[col * W_STR + c * 32 + k0 + q];
                    uint32_t bh1 = uWh[col * W_STR + c * 32 + k0 + q + 4];
                    uint32_t bl0 = uWl[col * A_STR + k0 + q];
                    uint32_t bl1 = uWl[col * A_STR + k0 + q + 4];
#pragma unroll
                    for (int mt = 0; mt < 2; mt++) {
                        mma8(accP[mt][nt], ah[mt][0], ah[mt][1], ah[mt][2], ah[mt][3], bh0, bh1);
                        mma8(accQ[mt][nt], ah[mt][0], ah[mt][1], ah[mt][2], ah[mt][3], bl0, bl1);
                        mma8(accQ[mt][nt], al[mt][0], al[mt][1], al[mt][2], al[mt][3], bh0, bh1);
                    }
                }
            }
            __syncthreads();
        }

        // ---------------- epilogue: accs -> stage -> LSTM cell ----------------
#pragma unroll
        for (int mt = 0; mt < 2; mt++)
#pragma unroll
            for (int nt = 0; nt < 2; nt++) {
                const int r0m  = wr * 32 + mt * 16 + g;
                const int col0 = wc * 16 + nt * 8 + 2 * q;
                stg[r0m * 65 + col0]           = accP[mt][nt][0] + accQ[mt][nt][0];
                stg[r0m * 65 + col0 + 1]       = accP[mt][nt][1] + accQ[mt][nt][1];
                stg[(r0m + 8) * 65 + col0]     = accP[mt][nt][2] + accQ[mt][nt][2];
                stg[(r0m + 8) * 65 + col0 + 1] = accP[mt][nt][3] + accQ[mt][nt][3];
            }
        __syncthreads();
        {
            const int r = tid >> 2, ei0 = (tid & 3) * 4;
            const int b = bb0 + r;
            const int nb = (t + 1) & 1;
            float hrow[4];
#pragma unroll
            for (int x = 0; x < 4; x++) {
                int ei = ei0 + x;
                float iv = stg[r * 65 + 0  + ei] + sBias[0 * 16 + ei];
                float fv = stg[r * 65 + 16 + ei] + sBias[1 * 16 + ei];
                float gv = stg[r * 65 + 32 + ei] + sBias[2 * 16 + ei];
                float ov = stg[r * 65 + 48 + ei] + sBias[3 * 16 + ei];
                float i_ = sigm(iv), f_ = sigm(fv), g_ = tanhf(gv), o_ = sigm(ov);
                float cn = f_ * creg[x] + i_ * g_;
                creg[x] = cn;
                hrow[x] = o_ * tanhf(cn);
            }
            *(float4*)(&g_h[nb][b * EMB + e0 + ei0]) =
                make_float4(hrow[0], hrow[1], hrow[2], hrow[3]);
        }

        // ---------------- bt-group barrier (16 blocks) ----------------
        __syncthreads();
        if (tid == 0) {
            __threadfence();
            atomicAdd((unsigned*)bar, 1u);
            const unsigned tgt = (unsigned)(t + 1) * 16u;
            while (*bar < tgt) __nanosleep(32);
        }
        __syncthreads();
    }
}

// -------------------- launch --------------------
extern "C" void kernel_launch(void* const* d_in, const int* in_sizes, int n_in,
                              void* d_out, int out_size) {
    const float* x0    = (const float*)d_in[0];
    const float* x1    = (const float*)d_in[1];
    const float* x2    = (const float*)d_in[2];
    // d_in[3] = x_lens (unused)
    const float* gum   = (const float*)d_in[4];
    const float* W0    = (const float*)d_in[5];
    const float* b0    = (const float*)d_in[6];
    const float* W1    = (const float*)d_in[7];
    const float* b1    = (const float*)d_in[8];
    const float* W_ih  = (const float*)d_in[9];
    const float* W_hh  = (const float*)d_in[10];
    const float* b_ih  = (const float*)d_in[11];
    const float* b_hh  = (const float*)d_in[12];
    const float* W_dec = (const float*)d_in[13];
    const float* b_dec = (const float*)d_in[14];
    float* out = (float*)d_out;

    init_kernel<<<(BATCH * EMB + 255) / 256, 256>>>();
    wsplit_kernel<<<(1024 * KPAD + 255) / 256, 256>>>(W_ih, W_hh);

    size_t smem1 = (size_t)(40 * 300 + 40 * 76) * sizeof(float);
    cudaFuncSetAttribute(phase1_kernel,
                         cudaFuncAttributeMaxDynamicSharedMemorySize, (int)smem1);
    phase1_kernel<<<NROWS / 32, 320, smem1>>>(x0, x1, x2, W0, b0, W1, b1);

    size_t smemP = (size_t)SMEM_F * sizeof(float);   // 194816 B
    cudaFuncSetAttribute(persist_kernel,
                         cudaFuncAttributeMaxDynamicSharedMemorySize, (int)smemP);
    persist_kernel<<<NBLK, THR, smemP>>>(W_ih, W_hh, b_ih, b_hh,
                                         W_dec, b_dec, gum, out);
}

// round 13
// speedup vs baseline: 1.6849x; 1.0720x over previous
#include <cuda_runtime.h>
#include <math.h>
#include <stdint.h>

typedef unsigned long long ull;

#define S_LEN   128
#define BATCH   1024
#define D0      300
#define D1      74
#define D2      35
#define HID     40
#define EMB     256
#define MM      3
#define RED_DIM 115            // 2*HID + D2
#define LSTM_IN 121            // RED_DIM + 2*MM
#define KTOT    377            // LSTM_IN + EMB
#define KPAD    384            // 12 chunks * 32
#define NCH     12
#define NROWS   (S_LEN*BATCH)
#define NBLK    128
#define THR     512

#define W_STR   388            // resident W_hi stride (mod 32 == 4: conflict-free frags)
#define A_STR   36             // A / W_lo chunk stride (mod 32 == 4)
#define RSTR    96             // red-split array stride (chunks 0..2 only)
#define HP_STR  272            // h-split padded stride: global k maps to idx k-112 (16B-aligned)

// ---- smem layout (float offsets) — identical to R9 ----
#define OFF_WHI  0                               // 64*388      = 24832
#define OFF_WLO  (OFF_WHI + 64 * W_STR)          // 2*64*36     = 4608
#define OFF_AHI  (OFF_WLO + 2 * 64 * A_STR)      // 2*128*36    = 9216
#define OFF_ALO  (OFF_AHI + 2 * 128 * A_STR)     // 9216
#define OFF_PREV (OFF_ALO + 2 * 128 * A_STR)     // 768
#define OFF_BIAS (OFF_PREV + 128 * 6)            // 64
#define SMEM_F   (OFF_BIAS + 64)                 // 48704 floats = 194816 B
// epilogue stage (128*65=8320 floats) aliases the A buffers at OFF_AHI

// ---------------- device scratch ----------------
__device__ float g_reduced[(size_t)NROWS * RED_DIM];
__device__ float g_red_hi[(size_t)NROWS * RSTR];     // tf32 hi of reduced, k<96
__device__ float g_red_lo[(size_t)NROWS * RSTR];     // tf32 lo
__device__ float g_h[2][BATCH * EMB];                // fp32 h (decoder + chunk-3 fringe)
__device__ float g_Hhi[2][BATCH * HP_STR];           // tf32 hi of h at idx = k-112 (k=121+col)
__device__ float g_Hlo[2][BATCH * HP_STR];           // pad idx 0..8 / 265..271 must be zero
__device__ float g_wlo[1024 * KPAD];
__device__ unsigned g_counts[8];

__device__ __forceinline__ float sigm(float x) { return 1.f / (1.f + expf(-x)); }
__device__ __forceinline__ float to_tf32(float x) {
    float r; asm("cvt.rna.tf32.f32 %0, %1;" : "=f"(r) : "f"(x)); return r;
}
__device__ __forceinline__ uint32_t smem_u32(const void* p) {
    uint32_t a;
    asm("{ .reg .u64 t; cvta.to.shared.u64 t, %1; cvt.u32.u64 %0, t; }" : "=r"(a) : "l"(p));
    return a;
}
// .cg = L2 path (no L1) — avoids stale-L1 on cross-SM h data
__device__ __forceinline__ void cp_async16(uint32_t dst, const float* src) {
    asm volatile("cp.async.cg.shared.global [%0], [%1], 16;" :: "r"(dst), "l"(src));
}
#define CP_COMMIT() asm volatile("cp.async.commit_group;" ::: "memory")
#define CP_WAIT0()  asm volatile("cp.async.wait_group 0;" ::: "memory")

__device__ __forceinline__ void mma8(float* d,
        uint32_t a0, uint32_t a1, uint32_t a2, uint32_t a3,
        uint32_t b0, uint32_t b1) {
    asm volatile(
        "mma.sync.aligned.m16n8k8.row.col.f32.tf32.tf32.f32 "
        "{%0,%1,%2,%3}, {%4,%5,%6,%7}, {%8,%9}, {%0,%1,%2,%3};"
        : "+f"(d[0]), "+f"(d[1]), "+f"(d[2]), "+f"(d[3])
        : "r"(a0), "r"(a1), "r"(a2), "r"(a3), "r"(b0), "r"(b1));
}

// -------------------- init --------------------
// Both ping-pong buffers of g_Hhi/g_Hlo zeroed: the epilogue only writes
// idx 9..264; the pad (0..8, 265..271) is read by chunk 11's async feed.
__global__ void init_kernel() {
    int i = blockIdx.x * blockDim.x + threadIdx.x;
    if (i < 8) g_counts[i] = 0u;
    if (i < BATCH * EMB) { g_h[0][i] = 0.f; g_h[1][i] = 0.f; }
    if (i < BATCH * HP_STR) {
        g_Hhi[0][i] = 0.f; g_Hlo[0][i] = 0.f;
        g_Hhi[1][i] = 0.f; g_Hlo[1][i] = 0.f;
    }
}

// -------------------- W low-part split --------------------
__global__ void wsplit_kernel(const float* __restrict__ W_ih, const float* __restrict__ W_hh) {
    int idx = blockIdx.x * blockDim.x + threadIdx.x;
    if (idx >= 1024 * KPAD) return;
    int grow = idx / KPAD, k = idx % KPAD;
    float w;
    if (k < LSTM_IN)     w = W_ih[grow * LSTM_IN + k];
    else if (k < KTOT)   w = W_hh[grow * EMB + (k - LSTM_IN)];
    else                 w = 0.f;
    g_wlo[idx] = to_tf32(w - to_tf32(w));
}

// -------------------- reduced split (k < 96, chunks 0..2) --------------------
__global__ void redsplit_kernel() {
    int idx = blockIdx.x * blockDim.x + threadIdx.x;
    if (idx >= NROWS * RSTR) return;
    int row = idx / RSTR, k = idx % RSTR;
    float v = g_reduced[(size_t)row * RED_DIM + k];
    float hi = to_tf32(v);
    g_red_hi[idx] = hi;
    g_red_lo[idx] = to_tf32(v - hi);
}

// -------------------- phase 1 (proven) --------------------
__global__ void phase1_kernel(const float* __restrict__ x0, const float* __restrict__ x1,
                              const float* __restrict__ x2,
                              const float* __restrict__ W0, const float* __restrict__ b0p,
                              const float* __restrict__ W1, const float* __restrict__ b1p) {
    extern __shared__ float sm[];
    float* sW0 = sm;
    float* sW1 = sm + 40 * 300;
    const int tid = threadIdx.x;

    for (int i = tid; i < 40 * 300; i += 320) sW0[i] = W0[i];
    for (int i = tid; i < 40 * 76; i += 320) {
        int r = i / 76, c = i % 76;
        sW1[i] = (c < D1) ? W1[r * D1 + c] : 0.f;
    }
    __syncthreads();

    const int r0 = blockIdx.x * 32;
    const int o  = tid % 40;
    const int rb = (tid / 40) * 4;
    {
        const float bv = b0p[o];
        float acc[4] = {bv, bv, bv, bv};
        const float4* wv = (const float4*)(sW0 + o * D0);
        const float4* xr[4];
#pragma unroll
        for (int j = 0; j < 4; j++) xr[j] = (const float4*)(x0 + (size_t)(r0 + rb + j) * D0);
#pragma unroll 5
        for (int k4 = 0; k4 < 75; k4++) {
            float4 w = wv[k4];
#pragma unroll
            for (int j = 0; j < 4; j++) {
                float4 a = __ldg(&xr[j][k4]);
                acc[j] += w.x * a.x + w.y * a.y + w.z * a.z + w.w * a.w;
            }
        }
#pragma unroll
        for (int j = 0; j < 4; j++)
            g_reduced[(size_t)(r0 + rb + j) * RED_DIM + o] = acc[j];
    }
    {
        const float bv = b1p[o];
        float acc[4] = {bv, bv, bv, bv};
        const float2* wv = (const float2*)(sW1 + o * 76);
        const float2* xr[4];
#pragma unroll
        for (int j = 0; j < 4; j++) xr[j] = (const float2*)(x1 + (size_t)(r0 + rb + j) * D1);
#pragma unroll 4
        for (int k2 = 0; k2 < 37; k2++) {
            float2 w = wv[k2];
#pragma unroll
            for (int j = 0; j < 4; j++) {
                float2 a = __ldg(&xr[j][k2]);
                acc[j] += w.x * a.x + w.y * a.y;
            }
        }
#pragma unroll
        for (int j = 0; j < 4; j++)
            g_reduced[(size_t)(r0 + rb + j) * RED_DIM + HID + o] = acc[j];
    }
    for (int i = tid; i < 32 * D2; i += 320) {
        int r = i / D2, c = i % D2;
        g_reduced[(size_t)(r0 + r) * RED_DIM + 2 * HID + c] = x2[(size_t)(r0 + r) * D2 + c];
    }
}

// -------------------- persistent mma.sync kernel: async feed, R9-exact math --------------------
// grid 128 (bt 0..7 x et 0..15), block 512 = 16 warps (4x4). MMA loop and all
// accumulation byte-identical to R9 (bit-exact outputs). A/W_lo operands arrive
// via cp.async.cg from pre-split globals; chunk 3 (mixed red|sPrev|h) keeps the
// R9 register path with identical values.
__global__ void __launch_bounds__(THR, 1) persist_kernel(
    const float* __restrict__ W_ih, const float* __restrict__ W_hh,
    const float* __restrict__ b_ih, const float* __restrict__ b_hh,
    const float* __restrict__ W_dec, const float* __restrict__ b_dec,
    const float* __restrict__ gum, float* __restrict__ out) {

    extern __shared__ float smf[];

    const int tid  = threadIdx.x;
    const int lane = tid & 31;
    const int warp = tid >> 5;                 // 0..15
    const int wr   = warp & 3;
    const int wc   = warp >> 2;
    const int bt   = blockIdx.x >> 4;
    const int et   = blockIdx.x & 15;
    const int bb0  = bt * 128;
    const int e0   = et * 16;

    const int g    = lane >> 2;
    const int q    = lane & 3;

    float* sWhi  = smf + OFF_WHI;
    float* sWlo  = smf + OFF_WLO;
    float* sAhi  = smf + OFF_AHI;
    float* sAlo  = smf + OFF_ALO;
    float* sPrev = smf + OFF_PREV;
    float* sBias = smf + OFF_BIAS;
    float* stg   = smf + OFF_AHI;

    const uint32_t sAhi_u = smem_u32(sAhi);
    const uint32_t sAlo_u = smem_u32(sAlo);
    const uint32_t sWlo_u = smem_u32(sWlo);

    // ---- one-time: resident W_hi (tf32-rounded), bias ----
    for (int i = tid; i < 64 * KPAD; i += THR) {
        int col = i / KPAD, k = i % KPAD;
        int grow = (col >> 4) * EMB + e0 + (col & 15);
        float w;
        if (k < LSTM_IN)     w = W_ih[grow * LSTM_IN + k];
        else if (k < KTOT)   w = W_hh[grow * EMB + (k - LSTM_IN)];
        else                 w = 0.f;
        sWhi[col * W_STR + k] = to_tf32(w);
    }
    if (tid < 64) {
        int gg = tid >> 4, ei = tid & 15;
        sBias[tid] = b_ih[gg * EMB + e0 + ei] + b_hh[gg * EMB + e0 + ei];
    }
    __syncthreads();

    float creg[4];
#pragma unroll
    for (int j = 0; j < 4; j++) creg[j] = 0.f;

    // ---- async feed mappings ----
    const int pr   = tid >> 2;                 // A row 0..127
    const int seg8 = (tid & 3) * 8;            // A k-offset 0,8,16,24
    const int pb   = bb0 + pr;
    const int pwc  = tid >> 3;                 // W col 0..63
    const int pwk  = (tid & 7) * 4;            // W k-offset 0..28
    const int pwrow = (pwc >> 4) * EMB + e0 + (pwc & 15);

    volatile unsigned* bar = &g_counts[bt];

    for (int t = 0; t <= S_LEN; t++) {
        const int hb = t & 1;
        const float* __restrict__ hprev = g_h[hb];
        const float* __restrict__ red_t = g_reduced + (size_t)t * BATCH * RED_DIM;
        const float* __restrict__ Hhi_t = g_Hhi[hb];
        const float* __restrict__ Hlo_t = g_Hlo[hb];

        // issue helpers (values identical to R9's register-staged splits)
        auto issueA = [&](int c, int nbuf) {
            const float *sh, *sl;
            if (c < 3) {
                // R12 BUG WAS HERE: missing the t*BATCH row offset.
                size_t o = ((size_t)t * BATCH + pb) * RSTR + c * 32 + seg8;
                sh = g_red_hi + o; sl = g_red_lo + o;
            } else {
                size_t o = (size_t)pb * HP_STR + (c * 32 - 112) + seg8;
                sh = Hhi_t + o; sl = Hlo_t + o;
            }
            uint32_t off = (uint32_t)((nbuf * 128 * A_STR + pr * A_STR + seg8) * 4);
            cp_async16(sAhi_u + off, sh);
            cp_async16(sAhi_u + off + 16, sh + 4);
            cp_async16(sAlo_u + off, sl);
            cp_async16(sAlo_u + off + 16, sl + 4);
        };
        auto issueW = [&](int c, int nbuf) {
            uint32_t dw = sWlo_u + (uint32_t)((nbuf * 64 * A_STR + pwc * A_STR + pwk) * 4);
            cp_async16(dw, g_wlo + (size_t)pwrow * KPAD + c * 32 + pwk);
        };

        // ---- pre-issue chunks 0 and 1 (hidden under the decoder) ----
        if (t < S_LEN) {
            issueA(0, 0); issueW(0, 0); CP_COMMIT();
            issueA(1, 1); issueW(1, 1); CP_COMMIT();
        }

        // ---------------- decoder prologue for step t-1 (bit-exact R9) ----------------
        if (t == 0) {
            for (int i = tid; i < 128 * 6; i += THR) sPrev[i] = 0.f;
        } else {
            const int tprev = t - 1;
            const bool wrt = (et == 0);
            for (int r2 = 0; r2 < 8; r2++) {
                const int rloc = warp * 8 + r2;
                const int b = bb0 + rloc;
                float hv[8];
#pragma unroll
                for (int i = 0; i < 8; i++) hv[i] = __ldcg(&hprev[b * EMB + lane + 32 * i]);
                float lg[6];
#pragma unroll
                for (int mo = 0; mo < 6; mo++) {
                    float p = 0.f;
#pragma unroll
                    for (int i = 0; i < 8; i++)
                        p += hv[i] * __ldg(&W_dec[mo * EMB + lane + 32 * i]);
                    p += __shfl_xor_sync(0xffffffffu, p, 16);
                    p += __shfl_xor_sync(0xffffffffu, p, 8);
                    p += __shfl_xor_sync(0xffffffffu, p, 4);
                    p += __shfl_xor_sync(0xffffffffu, p, 2);
                    p += __shfl_xor_sync(0xffffffffu, p, 1);
                    p += __ldg(&b_dec[mo]);
                    lg[mo] = p;
                    if (lane == mo) sPrev[rloc * 6 + mo] = p;
                }
                if (wrt && lane < MM) {
                    const int m = lane;
                    size_t gbase = ((size_t)tprev * (MM * BATCH) + m * BATCH + b) * 2;
                    float u0 = gum[gbase], u1 = gum[gbase + 1];
                    float gg0 = -logf(-logf(u0));
                    float gg1 = -logf(-logf(u1));
                    float l0 = lg[2 * m], l1 = lg[2 * m + 1];
                    out[((size_t)tprev * MM + m) * BATCH + b] =
                        (l1 + gg1 > l0 + gg0) ? 1.f : 0.f;
                    size_t lbase = (size_t)S_LEN * MM * BATCH +
                                   (((size_t)tprev * MM + m) * BATCH + b) * 2;
                    out[lbase]     = l0;
                    out[lbase + 1] = l1;
                }
            }
        }
        if (t == S_LEN) break;

        CP_WAIT0();          // chunks 0 and 1 resident
        __syncthreads();     // sPrev + buffers visible block-wide

        float accP[2][2][4], accQ[2][2][4];
#pragma unroll
        for (int mt = 0; mt < 2; mt++)
#pragma unroll
            for (int nt = 0; nt < 2; nt++)
#pragma unroll
                for (int x = 0; x < 4; x++) { accP[mt][nt][x] = 0.f; accQ[mt][nt][x] = 0.f; }

        float pf[8];

        // ---------------- chunk loop (1 sync/chunk) ----------------
        for (int c = 0; c < NCH; c++) {
            const int buf = c & 1;

            // feed chunk c+1 into the buffer freed at the last sync
            if (c >= 1 && c + 1 < NCH) {
                const int nc = c + 1, nbuf = nc & 1;
                if (nc == 3) {
                    // register path: values identical to R9 (red | sPrev | h fringe)
                    float* dAh = sAhi + nbuf * 128 * A_STR;
                    float* dAl = sAlo + nbuf * 128 * A_STR;
                    float4 vh0, vh1, vl0, vl1;
                    float* ph0 = (float*)&vh0; float* pl0 = (float*)&vl0;
                    float* ph1 = (float*)&vh1; float* pl1 = (float*)&vl1;
#pragma unroll
                    for (int x = 0; x < 4; x++) {
                        float hi = to_tf32(pf[x]);
                        ph0[x] = hi; pl0[x] = to_tf32(pf[x] - hi);
                        float hi2 = to_tf32(pf[x + 4]);
                        ph1[x] = hi2; pl1[x] = to_tf32(pf[x + 4] - hi2);
                    }
                    *(float4*)(dAh + pr * A_STR + seg8)     = vh0;
                    *(float4*)(dAh + pr * A_STR + seg8 + 4) = vh1;
                    *(float4*)(dAl + pr * A_STR + seg8)     = vl0;
                    *(float4*)(dAl + pr * A_STR + seg8 + 4) = vl1;
                    issueW(3, nbuf); CP_COMMIT();
                } else {
                    issueA(nc, nbuf); issueW(nc, nbuf); CP_COMMIT();
                }
            }
            // load chunk-3 mixed values early (consumed at c==2 staging)
            if (c == 0) {
#pragma unroll
                for (int x = 0; x < 8; x++) {
                    int kg = 96 + seg8 + x;
                    float v;
                    if (kg < RED_DIM)       v = __ldg(&red_t[(size_t)pb * RED_DIM + kg]);
                    else if (kg < LSTM_IN)  v = sPrev[pr * 6 + (kg - RED_DIM)];
                    else                    v = __ldcg(&hprev[pb * EMB + (kg - LSTM_IN)]);
                    pf[x] = v;
                }
            }

            // ---- MMA on buf: byte-identical to R9 ----
            const uint32_t* uAh = (const uint32_t*)(sAhi + buf * 128 * A_STR);
            const uint32_t* uAl = (const uint32_t*)(sAlo + buf * 128 * A_STR);
            const uint32_t* uWh = (const uint32_t*)sWhi;
            const uint32_t* uWl = (const uint32_t*)(sWlo + buf * 64 * A_STR);
#pragma unroll
            for (int kk = 0; kk < 4; kk++) {
                const int k0 = kk * 8;
                uint32_t ah[2][4], al[2][4];
#pragma unroll
                for (int mt = 0; mt < 2; mt++) {
                    const int r0m = wr * 32 + mt * 16 + g;
                    ah[mt][0] = uAh[r0m * A_STR + k0 + q];
                    ah[mt][1] = uAh[(r0m + 8) * A_STR + k0 + q];
                    ah[mt][2] = uAh[r0m * A_STR + k0 + q + 4];
                    ah[mt][3] = uAh[(r0m + 8) * A_STR + k0 + q + 4];
                    al[mt][0] = uAl[r0m * A_STR + k0 + q];
                    al[mt][1] = uAl[(r0m + 8) * A_STR + k0 + q];
                    al[mt][2] = uAl[r0m * A_STR + k0 + q + 4];
                    al[mt][3] = uAl[(r0m + 8) * A_STR + k0 + q + 4];
                }
#pragma unroll
                for (int nt = 0; nt < 2; nt++) {
                    const int col = wc * 16 + nt * 8 + g;
                    uint32_t bh0 = uWh[col * W_STR + c * 32 + k0 + q];
                    uint32_t bh1 = uWh[col * W_STR + c * 32 + k0 + q + 4];
                    uint32_t bl0 = uWl[col * A_STR + k0 + q];
                    uint32_t bl1 = uWl[col * A_STR + k0 + q + 4];
#pragma unroll
                    for (int mt = 0; mt < 2; mt++) {
                        mma8(accP[mt][nt], ah[mt][0], ah[mt][1], ah[mt][2], ah[mt][3], bh0, bh1);
                        mma8(accQ[mt][nt], ah[mt][0], ah[mt][1], ah[mt][2], ah[mt][3], bl0, bl1);
                        mma8(accQ[mt][nt], al[mt][0], al[mt][1], al[mt][2], al[mt][3], bh0, bh1);
                    }
                }
            }
            if (c + 1 < NCH) CP_WAIT0();
            __syncthreads();
        }

        // ---------------- epilogue: accs -> stage -> LSTM cell (bit-exact R9) ----------------
#pragma unroll
        for (int mt = 0; mt < 2; mt++)
#pragma unroll
            for (int nt = 0; nt < 2; nt++) {
                const int r0m  = wr * 32 + mt * 16 + g;
                const int col0 = wc * 16 + nt * 8 + 2 * q;
                stg[r0m * 65 + col0]           = accP[mt][nt][0] + accQ[mt][nt][0];
                stg[r0m * 65 + col0 + 1]       = accP[mt][nt][1] + accQ[mt][nt][1];
                stg[(r0m + 8) * 65 + col0]     = accP[mt][nt][2] + accQ[mt][nt][2];
                stg[(r0m + 8) * 65 + col0 + 1] = accP[mt][nt][3] + accQ[mt][nt][3];
            }
        __syncthreads();
        {
            const int r = tid >> 2, ei0 = (tid & 3) * 4;
            const int b = bb0 + r;
            const int nb = (t + 1) & 1;
            float hrow[4];
#pragma unroll
            for (int x = 0; x < 4; x++) {
                int ei = ei0 + x;
                float iv = stg[r * 65 + 0  + ei] + sBias[0 * 16 + ei];
                float fv = stg[r * 65 + 16 + ei] + sBias[1 * 16 + ei];
                float gv = stg[r * 65 + 32 + ei] + sBias[2 * 16 + ei];
                float ov = stg[r * 65 + 48 + ei] + sBias[3 * 16 + ei];
                float i_ = sigm(iv), f_ = sigm(fv), g_ = tanhf(gv), o_ = sigm(ov);
                float cn = f_ * creg[x] + i_ * g_;
                creg[x] = cn;
                hrow[x] = o_ * tanhf(cn);
            }
            *(float4*)(&g_h[nb][b * EMB + e0 + ei0]) =
                make_float4(hrow[0], hrow[1], hrow[2], hrow[3]);
            // pre-split h for next step's async A feed (same values as R9's
            // in-register split: tf32(h), tf32(h - tf32(h)))
#pragma unroll
            for (int x = 0; x < 4; x++) {
                float hv2 = hrow[x];
                float hhi = to_tf32(hv2);
                int hidx = b * HP_STR + 9 + e0 + ei0 + x;   // idx = (121+col) - 112
                g_Hhi[nb][hidx] = hhi;
                g_Hlo[nb][hidx] = to_tf32(hv2 - hhi);
            }
        }

        // ---------------- bt-group barrier (16 blocks) ----------------
        __syncthreads();
        if (tid == 0) {
            __threadfence();
            atomicAdd((unsigned*)bar, 1u);
            const unsigned tgt = (unsigned)(t + 1) * 16u;
            while (*bar < tgt) __nanosleep(32);
        }
        __syncthreads();
    }
}

// -------------------- launch --------------------
extern "C" void kernel_launch(void* const* d_in, const int* in_sizes, int n_in,
                              void* d_out, int out_size) {
    const float* x0    = (const float*)d_in[0];
    const float* x1    = (const float*)d_in[1];
    const float* x2    = (const float*)d_in[2];
    // d_in[3] = x_lens (unused)
    const float* gum   = (const float*)d_in[4];
    const float* W0    = (const float*)d_in[5];
    const float* b0    = (const float*)d_in[6];
    const float* W1    = (const float*)d_in[7];
    const float* b1    = (const float*)d_in[8];
    const float* W_ih  = (const float*)d_in[9];
    const float* W_hh  = (const float*)d_in[10];
    const float* b_ih  = (const float*)d_in[11];
    const float* b_hh  = (const float*)d_in[12];
    const float* W_dec = (const float*)d_in[13];
    const float* b_dec = (const float*)d_in[14];
    float* out = (float*)d_out;

    init_kernel<<<(BATCH * HP_STR + 255) / 256, 256>>>();
    wsplit_kernel<<<(1024 * KPAD + 255) / 256, 256>>>(W_ih, W_hh);

    size_t smem1 = (size_t)(40 * 300 + 40 * 76) * sizeof(float);
    cudaFuncSetAttribute(phase1_kernel,
                         cudaFuncAttributeMaxDynamicSharedMemorySize, (int)smem1);
    phase1_kernel<<<NROWS / 32, 320, smem1>>>(x0, x1, x2, W0, b0, W1, b1);

    redsplit_kernel<<<(NROWS * RSTR + 255) / 256, 256>>>();

    size_t smemP = (size_t)SMEM_F * sizeof(float);   // 194816 B
    cudaFuncSetAttribute(persist_kernel,
                         cudaFuncAttributeMaxDynamicSharedMemorySize, (int)smemP);
    persist_kernel<<<NBLK, THR, smemP>>>(W_ih, W_hh, b_ih, b_hh,
                                         W_dec, b_dec, gum, out);
}

// round 14
// speedup vs baseline: 1.9340x; 1.1478x over previous
#include <cuda_runtime.h>
#include <math.h>
#include <stdint.h>

typedef unsigned long long ull;

#define S_LEN   128
#define BATCH   1024
#define D0      300
#define D1      74
#define D2      35
#define HID     40
#define EMB     256
#define MM      3
#define RED_DIM 115            // 2*HID + D2
#define LSTM_IN 121            // RED_DIM + 2*MM
#define KTOT    377            // LSTM_IN + EMB
#define NCH     12
#define NROWS   (S_LEN*BATCH)
#define NBLK    128
#define THR     256

// ---- fragment-major smem layout (float offsets) ----
// W_hi: [c 12][ntile 8][ktile 4][lane 32] float2           = 24576 floats
// W_lo: 2 bufs x [ntile 8][ktile 4][lane 32] float2        = 2*2048
// A hi/lo: 2 bufs x [rtile 8][ktile 4][lane 32] float4     = 2*4096 each
#define OFF_WHIF 0
#define OFF_WLOF 24576
#define OFF_AHI  28672
#define OFF_ALO  36864
#define OFF_PREV 45056          // 128*6
#define OFF_BIAS 45824          // 64
#define SMEM_F   45888          // 183552 bytes
// epilogue stage (128*65 = 8320 floats) aliases [OFF_AHI, OFF_AHI+8192)

// ---------------- device scratch ----------------
__device__ float  g_reduced[(size_t)NROWS * RED_DIM];
// fragment-major pre-split inputs: [t][bt 8][c 3][ft 1024] float4 (slot order:
// s0=(rA,kA) s1=(rB,kA) s2=(rA,kB) s3=(rB,kB); rA=rtile*16+g, rB=rA+8,
// kA=c*32+ktile*8+q, kB=kA+4; ft=(rtile*4+ktile)*32+g*4+q)
__device__ float4 g_redF_hi[(size_t)S_LEN * 8 * 3 * 1024];
__device__ float4 g_redF_lo[(size_t)S_LEN * 8 * 3 * 1024];
// fragment-major pre-split h: [hb 2][bt 8][c-4 8][ft 1024] float4 (pads stay 0)
__device__ float4 g_HF_hi[2 * 8 * 8 * 1024];
__device__ float4 g_HF_lo[2 * 8 * 8 * 1024];
// fragment-major W_lo: [et 16][c 12][ntile 8][ktile 4][lane 32] float2
__device__ float  g_wloF[16 * 12 * 2048];
__device__ float  g_h[2][BATCH * EMB];               // fp32 h (decoder + chunk-3 fringe)
__device__ unsigned g_counts[8];

__device__ __forceinline__ float sigm(float x) { return 1.f / (1.f + expf(-x)); }
__device__ __forceinline__ float to_tf32(float x) {
    float r; asm("cvt.rna.tf32.f32 %0, %1;" : "=f"(r) : "f"(x)); return r;
}
__device__ __forceinline__ uint32_t smem_u32(const void* p) {
    uint32_t a;
    asm("{ .reg .u64 t; cvta.to.shared.u64 t, %1; cvt.u32.u64 %0, t; }" : "=r"(a) : "l"(p));
    return a;
}
__device__ __forceinline__ void cp_async16(uint32_t dst, const void* src) {
    asm volatile("cp.async.cg.shared.global [%0], [%1], 16;" :: "r"(dst), "l"(src));
}
#define CP_COMMIT() asm volatile("cp.async.commit_group;" ::: "memory")
#define CP_WAIT0()  asm volatile("cp.async.wait_group 0;" ::: "memory")

__device__ __forceinline__ void mma8(float* d, float4 a, float2 b) {
    asm volatile(
        "mma.sync.aligned.m16n8k8.row.col.f32.tf32.tf32.f32 "
        "{%0,%1,%2,%3}, {%4,%5,%6,%7}, {%8,%9}, {%0,%1,%2,%3};"
        : "+f"(d[0]), "+f"(d[1]), "+f"(d[2]), "+f"(d[3])
        : "r"(__float_as_uint(a.x)), "r"(__float_as_uint(a.y)),
          "r"(__float_as_uint(a.z)), "r"(__float_as_uint(a.w)),
          "r"(__float_as_uint(b.x)), "r"(__float_as_uint(b.y)));
}

// -------------------- init --------------------
__global__ void init_kernel() {
    int i = blockIdx.x * blockDim.x + threadIdx.x;
    if (i < 8) g_counts[i] = 0u;
    if (i < BATCH * EMB) { g_h[0][i] = 0.f; g_h[1][i] = 0.f; }
    if (i < 2 * 8 * 8 * 1024 * 4) {        // zero ALL of both h-frag buffers (pads!)
        ((float*)g_HF_hi)[i] = 0.f;
        ((float*)g_HF_lo)[i] = 0.f;
    }
}

// -------------------- W_lo fragment split --------------------
__global__ void wsplitF_kernel(const float* __restrict__ W_ih, const float* __restrict__ W_hh) {
    int i = blockIdx.x * blockDim.x + threadIdx.x;   // float2 index
    if (i >= 16 * 12 * 1024) return;
    int lane_e = i & 31;
    int ktile  = (i >> 5) & 3;
    int ntile  = (i >> 7) & 7;
    int c      = (i >> 10) % 12;
    int et     = (i >> 10) / 12;
    int j    = ntile * 8 + (lane_e >> 2);
    int grow = (j >> 4) * EMB + et * 16 + (j & 15);
    int k0   = c * 32 + ktile * 8 + (lane_e & 3);
#pragma unroll
    for (int s = 0; s < 2; s++) {
        int k = k0 + 4 * s;
        float w;
        if (k < LSTM_IN)     w = W_ih[grow * LSTM_IN + k];
        else if (k < KTOT)   w = W_hh[grow * EMB + (k - LSTM_IN)];
        else                 w = 0.f;
        g_wloF[(size_t)i * 2 + s] = to_tf32(w - to_tf32(w));
    }
}

// -------------------- reduced fragment split (chunks 0..2) --------------------
__global__ void redsplitF_kernel() {
    int i = blockIdx.x * blockDim.x + threadIdx.x;   // float4 index
    if (i >= S_LEN * 8 * 3 * 1024) return;
    int ft  = i & 1023;
    int c   = (i >> 10) % 3;
    int bt  = (i >> 10) / 3 % 8;
    int t   = (i >> 10) / 24;
    int rtile = ft >> 7, lane_e = ft & 31, ktile = (ft >> 5) & 3;
    int g = lane_e >> 2, q = lane_e & 3;
    int rA = bt * 128 + rtile * 16 + g;
    int kA = c * 32 + ktile * 8 + q;
    const float* src = g_reduced + (size_t)t * BATCH * RED_DIM;
    float v0 = src[(size_t)rA * RED_DIM + kA];
    float v1 = src[(size_t)(rA + 8) * RED_DIM + kA];
    float v2 = src[(size_t)rA * RED_DIM + kA + 4];
    float v3 = src[(size_t)(rA + 8) * RED_DIM + kA + 4];
    float h0 = to_tf32(v0), h1 = to_tf32(v1), h2 = to_tf32(v2), h3 = to_tf32(v3);
    g_redF_hi[i] = make_float4(h0, h1, h2, h3);
    g_redF_lo[i] = make_float4(to_tf32(v0 - h0), to_tf32(v1 - h1),
                               to_tf32(v2 - h2), to_tf32(v3 - h3));
}

// -------------------- phase 1 (proven) --------------------
__global__ void phase1_kernel(const float* __restrict__ x0, const float* __restrict__ x1,
                              const float* __restrict__ x2,
                              const float* __restrict__ W0, const float* __restrict__ b0p,
                              const float* __restrict__ W1, const float* __restrict__ b1p) {
    extern __shared__ float sm[];
    float* sW0 = sm;
    float* sW1 = sm + 40 * 300;
    const int tid = threadIdx.x;

    for (int i = tid; i < 40 * 300; i += 320) sW0[i] = W0[i];
    for (int i = tid; i < 40 * 76; i += 320) {
        int r = i / 76, c = i % 76;
        sW1[i] = (c < D1) ? W1[r * D1 + c] : 0.f;
    }
    __syncthreads();

    const int r0 = blockIdx.x * 32;
    const int o  = tid % 40;
    const int rb = (tid / 40) * 4;
    {
        const float bv = b0p[o];
        float acc[4] = {bv, bv, bv, bv};
        const float4* wv = (const float4*)(sW0 + o * D0);
        const float4* xr[4];
#pragma unroll
        for (int j = 0; j < 4; j++) xr[j] = (const float4*)(x0 + (size_t)(r0 + rb + j) * D0);
#pragma unroll 5
        for (int k4 = 0; k4 < 75; k4++) {
            float4 w = wv[k4];
#pragma unroll
            for (int j = 0; j < 4; j++) {
                float4 a = __ldg(&xr[j][k4]);
                acc[j] += w.x * a.x + w.y * a.y + w.z * a.z + w.w * a.w;
            }
        }
#pragma unroll
        for (int j = 0; j < 4; j++)
            g_reduced[(size_t)(r0 + rb + j) * RED_DIM + o] = acc[j];
    }
    {
        const float bv = b1p[o];
        float acc[4] = {bv, bv, bv, bv};
        const float2* wv = (const float2*)(sW1 + o * 76);
        const float2* xr[4];
#pragma unroll
        for (int j = 0; j < 4; j++) xr[j] = (const float2*)(x1 + (size_t)(r0 + rb + j) * D1);
#pragma unroll 4
        for (int k2 = 0; k2 < 37; k2++) {
            float2 w = wv[k2];
#pragma unroll
            for (int j = 0; j < 4; j++) {
                float2 a = __ldg(&xr[j][k2]);
                acc[j] += w.x * a.x + w.y * a.y;
            }
        }
#pragma unroll
        for (int j = 0; j < 4; j++)
            g_reduced[(size_t)(r0 + rb + j) * RED_DIM + HID + o] = acc[j];
    }
    for (int i = tid; i < 32 * D2; i += 320) {
        int r = i / D2, c = i % D2;
        g_reduced[(size_t)(r0 + r) * RED_DIM + 2 * HID + c] = x2[(size_t)(r0 + r) * D2 + c];
    }
}

// -------------------- persistent kernel: 8 warps, 32x32 tiles, frag-major ----
__global__ void __launch_bounds__(THR, 1) persist_kernel(
    const float* __restrict__ W_ih, const float* __restrict__ W_hh,
    const float* __restrict__ b_ih, const float* __restrict__ b_hh,
    const float* __restrict__ W_dec, const float* __restrict__ b_dec,
    const float* __restrict__ gum, float* __restrict__ out) {

    extern __shared__ float smf[];

    const int tid  = threadIdx.x;
    const int lane = tid & 31;
    const int warp = tid >> 5;                 // 0..7
    const int wr   = warp & 3;                 // row group (32 rows)
    const int wc   = warp >> 2;                // col group (32 cols)
    const int bt   = blockIdx.x >> 4;
    const int et   = blockIdx.x & 15;
    const int bb0  = bt * 128;
    const int e0   = et * 16;

    const int g = lane >> 2;
    const int q = lane & 3;

    float* sWhiF = smf + OFF_WHIF;
    float* sWloF = smf + OFF_WLOF;
    float* sAhiF = smf + OFF_AHI;
    float* sAloF = smf + OFF_ALO;
    float* sPrev = smf + OFF_PREV;
    float* sBias = smf + OFF_BIAS;
    float* stg   = smf + OFF_AHI;

    const uint32_t sAhi_u = smem_u32(sAhiF);
    const uint32_t sAlo_u = smem_u32(sAloF);
    const uint32_t sWlo_u = smem_u32(sWloF);

    // ---- one-time: resident W_hi fragment build; bias ----
    for (int i = tid; i < 24576; i += THR) {
        int slot = i & 1, i2 = i >> 1;
        int lane_e = i2 & 31, ktile = (i2 >> 5) & 3, ntile = (i2 >> 7) & 7, c = i2 >> 10;
        int j = ntile * 8 + (lane_e >> 2);
        int grow = (j >> 4) * EMB + e0 + (j & 15);
        int k = c * 32 + ktile * 8 + (lane_e & 3) + 4 * slot;
        float w;
        if (k < LSTM_IN)     w = W_ih[grow * LSTM_IN + k];
        else if (k < KTOT)   w = W_hh[grow * EMB + (k - LSTM_IN)];
        else                 w = 0.f;
        sWhiF[i] = to_tf32(w);
    }
    if (tid < 64) {
        int gg = tid >> 4, ei = tid & 15;
        sBias[tid] = b_ih[gg * EMB + e0 + ei] + b_hh[gg * EMB + e0 + ei];
    }
    __syncthreads();

    float creg[8];
#pragma unroll
    for (int j = 0; j < 8; j++) creg[j] = 0.f;

    volatile unsigned* bar = &g_counts[bt];

    for (int t = 0; t <= S_LEN; t++) {
        const int hb = t & 1;
        const float* __restrict__ hprev = g_h[hb];
        const float* __restrict__ red_t = g_reduced + (size_t)t * BATCH * RED_DIM;

        // issue helpers — fragment copies, values identical to R13's feeds
        auto issueA = [&](int c, int nbuf) {
            const float4 *sh, *sl;
            if (c < 3) {
                size_t o = (((size_t)t * 8 + bt) * 3 + c) << 10;
                sh = g_redF_hi + o; sl = g_redF_lo + o;
            } else {
                size_t o = (((size_t)hb * 8 + bt) * 8 + (c - 4)) << 10;
                sh = g_HF_hi + o; sl = g_HF_lo + o;
            }
            uint32_t dh = sAhi_u + (uint32_t)nbuf * 16384 + tid * 16;
            uint32_t dl = sAlo_u + (uint32_t)nbuf * 16384 + tid * 16;
#pragma unroll
            for (int jj = 0; jj < 4; jj++) {
                cp_async16(dh + jj * 4096, sh + tid + jj * 256);
                cp_async16(dl + jj * 4096, sl + tid + jj * 256);
            }
        };
        auto issueW = [&](int c, int nbuf) {
            const float* src = g_wloF + ((size_t)et * 12 + c) * 2048;
            uint32_t dw = sWlo_u + (uint32_t)nbuf * 8192 + tid * 16;
            cp_async16(dw, src + tid * 4);
            cp_async16(dw + 4096, src + (tid + 256) * 4);
        };

        // ---- pre-issue chunks 0 and 1 (hidden under the decoder) ----
        if (t < S_LEN) {
            issueA(0, 0); issueW(0, 0); CP_COMMIT();
            issueA(1, 1); issueW(1, 1); CP_COMMIT();
        }

        // ---------------- decoder prologue for step t-1 (bit-exact) ----------------
        if (t == 0) {
            for (int i = tid; i < 128 * 6; i += THR) sPrev[i] = 0.f;
        } else {
            const int tprev = t - 1;
            const bool wrt = (et == 0);
            for (int r2 = 0; r2 < 16; r2++) {
                const int rloc = warp * 16 + r2;
                const int b = bb0 + rloc;
                float hv[8];
#pragma unroll
                for (int i = 0; i < 8; i++) hv[i] = __ldcg(&hprev[b * EMB + lane + 32 * i]);
                float lg[6];
#pragma unroll
                for (int mo = 0; mo < 6; mo++) {
                    float p = 0.f;
#pragma unroll
                    for (int i = 0; i < 8; i++)
                        p += hv[i] * __ldg(&W_dec[mo * EMB + lane + 32 * i]);
                    p += __shfl_xor_sync(0xffffffffu, p, 16);
                    p += __shfl_xor_sync(0xffffffffu, p, 8);
                    p += __shfl_xor_sync(0xffffffffu, p, 4);
                    p += __shfl_xor_sync(0xffffffffu, p, 2);
                    p += __shfl_xor_sync(0xffffffffu, p, 1);
                    p += __ldg(&b_dec[mo]);
                    lg[mo] = p;
                    if (lane == mo) sPrev[rloc * 6 + mo] = p;
                }
                if (wrt && lane < MM) {
                    const int m = lane;
                    size_t gbase = ((size_t)tprev * (MM * BATCH) + m * BATCH + b) * 2;
                    float u0 = gum[gbase], u1 = gum[gbase + 1];
                    float gg0 = -logf(-logf(u0));
                    float gg1 = -logf(-logf(u1));
                    float l0 = lg[2 * m], l1 = lg[2 * m + 1];
                    out[((size_t)tprev * MM + m) * BATCH + b] =
                        (l1 + gg1 > l0 + gg0) ? 1.f : 0.f;
                    size_t lbase = (size_t)S_LEN * MM * BATCH +
                                   (((size_t)tprev * MM + m) * BATCH + b) * 2;
                    out[lbase]     = l0;
                    out[lbase + 1] = l1;
                }
            }
        }
        if (t == S_LEN) break;

        CP_WAIT0();
        __syncthreads();

        float accP[2][4][4], accQ[2][4][4];
#pragma unroll
        for (int mt = 0; mt < 2; mt++)
#pragma unroll
            for (int nt = 0; nt < 4; nt++)
#pragma unroll
                for (int x = 0; x < 4; x++) { accP[mt][nt][x] = 0.f; accQ[mt][nt][x] = 0.f; }

        float pf[16];   // chunk-3 mixed source values, fragment-ordered

        // ---------------- chunk loop (1 sync/chunk) ----------------
        for (int c = 0; c < NCH; c++) {
            const int buf = c & 1;

            if (c >= 1 && c + 1 < NCH) {
                const int nc = c + 1, nbuf = nc & 1;
                if (nc == 3) {
                    // register path: fragment-major STS.128, values identical to R13
                    float* dAh = sAhiF + nbuf * 4096;
                    float* dAl = sAloF + nbuf * 4096;
#pragma unroll
                    for (int jj = 0; jj < 4; jj++) {
                        int ft = tid + 256 * jj;
                        float4 vh, vl;
                        float* ph = (float*)&vh; float* pl = (float*)&vl;
#pragma unroll
                        for (int s = 0; s < 4; s++) {
                            float v = pf[jj * 4 + s];
                            float hi = to_tf32(v);
                            ph[s] = hi; pl[s] = to_tf32(v - hi);
                        }
                        ((float4*)dAh)[ft] = vh;
                        ((float4*)dAl)[ft] = vl;
                    }
                    issueW(3, nbuf); CP_COMMIT();
                } else {
                    issueA(nc, nbuf); issueW(nc, nbuf); CP_COMMIT();
                }
            }
            if (c == 0) {
                // gather chunk-3 mixed values in fragment order
#pragma unroll
                for (int jj = 0; jj < 4; jj++) {
                    int ft = tid + 256 * jj;
                    int rtile = ft >> 7, lane_e = ft & 31, ktile = (ft >> 5) & 3;
                    int gg2 = lane_e >> 2, qq = lane_e & 3;
                    int rA = rtile * 16 + gg2;
#pragma unroll
                    for (int s = 0; s < 4; s++) {
                        int r = rA + 8 * (s & 1);
                        int k = 96 + ktile * 8 + qq + 4 * (s >> 1);
                        float v;
                        if (k < RED_DIM)       v = __ldg(&red_t[(size_t)(bb0 + r) * RED_DIM + k]);
                        else if (k < LSTM_IN)  v = sPrev[r * 6 + (k - RED_DIM)];
                        else                   v = __ldcg(&hprev[(bb0 + r) * EMB + (k - LSTM_IN)]);
                        pf[jj * 4 + s] = v;
                    }
                }
            }

            // ---- MMA on buf: fragment loads (LDS.128 / LDS.64) ----
            const float4* fAh = (const float4*)(sAhiF + buf * 4096);
            const float4* fAl = (const float4*)(sAloF + buf * 4096);
            const float2* fWh = (const float2*)sWhiF;
            const float2* fWl = (const float2*)(sWloF + buf * 2048);
#pragma unroll
            for (int kk = 0; kk < 4; kk++) {
                float4 ah[2], al[2];
#pragma unroll
                for (int mt = 0; mt < 2; mt++) {
                    const int rt = wr * 2 + mt;
                    ah[mt] = fAh[(rt * 4 + kk) * 32 + lane];
                    al[mt] = fAl[(rt * 4 + kk) * 32 + lane];
                }
#pragma unroll
                for (int nt = 0; nt < 4; nt++) {
                    const int ntg = wc * 4 + nt;
                    float2 bh = fWh[((c * 8 + ntg) * 4 + kk) * 32 + lane];
                    float2 bl = fWl[(ntg * 4 + kk) * 32 + lane];
#pragma unroll
                    for (int mt = 0; mt < 2; mt++) {
                        mma8(accP[mt][nt], ah[mt], bh);
                        mma8(accQ[mt][nt], ah[mt], bl);
                        mma8(accQ[mt][nt], al[mt], bh);
                    }
                }
            }
            if (c + 1 < NCH) CP_WAIT0();
            __syncthreads();
        }

        // ---------------- epilogue: accs -> stage -> LSTM cell (bit-exact) ----------------
#pragma unroll
        for (int mt = 0; mt < 2; mt++)
#pragma unroll
            for (int nt = 0; nt < 4; nt++) {
                const int r0m  = wr * 32 + mt * 16 + g;
                const int col0 = wc * 32 + nt * 8 + 2 * q;
                stg[r0m * 65 + col0]           = accP[mt][nt][0] + accQ[mt][nt][0];
                stg[r0m * 65 + col0 + 1]       = accP[mt][nt][1] + accQ[mt][nt][1];
                stg[(r0m + 8) * 65 + col0]     = accP[mt][nt][2] + accQ[mt][nt][2];
                stg[(r0m + 8) * 65 + col0 + 1] = accP[mt][nt][3] + accQ[mt][nt][3];
            }
        __syncthreads();
        {
            const int r = tid >> 1, ei0 = (tid & 1) * 8;
            const int b = bb0 + r;
            const int nb = (t + 1) & 1;
            const int rtile = r >> 4, gg2 = r & 7, rh = (r >> 3) & 1;
            float hrow[8];
#pragma unroll
            for (int x = 0; x < 8; x++) {
                int ei = ei0 + x;
                float iv = stg[r * 65 + 0  + ei] + sBias[0 * 16 + ei];
                float fv = stg[r * 65 + 16 + ei] + sBias[1 * 16 + ei];
                float gv = stg[r * 65 + 32 + ei] + sBias[2 * 16 + ei];
                float ov = stg[r * 65 + 48 + ei] + sBias[3 * 16 + ei];
                float i_ = sigm(iv), f_ = sigm(fv), g_ = tanhf(gv), o_ = sigm(ov);
                float cn = f_ * creg[x] + i_ * g_;
                creg[x] = cn;
                hrow[x] = o_ * tanhf(cn);
            }
            float* hdst = &g_h[nb][b * EMB + e0 + ei0];
            *(float4*)(hdst)     = make_float4(hrow[0], hrow[1], hrow[2], hrow[3]);
            *(float4*)(hdst + 4) = make_float4(hrow[4], hrow[5], hrow[6], hrow[7]);
            // fragment-major h split for next step's async A feed (k >= 128 only;
            // k in [121,128) is served by the chunk-3 register path from g_h)
#pragma unroll
            for (int x = 0; x < 8; x++) {
                int k = 121 + e0 + ei0 + x;
                if (k < 128) continue;
                float hv2 = hrow[x];
                float hhi = to_tf32(hv2);
                int cK = k >> 5, ktile = (k >> 3) & 3, qq = k & 3, kh = (k >> 2) & 1;
                int ft = (rtile * 4 + ktile) * 32 + gg2 * 4 + qq;
                int s  = rh + 2 * kh;
                size_t fa = (((((size_t)nb * 8 + bt) * 8 + (cK - 4)) << 10) + ft) * 4 + s;
                ((float*)g_HF_hi)[fa] = hhi;
                ((float*)g_HF_lo)[fa] = to_tf32(hv2 - hhi);
            }
        }

        // ---------------- bt-group barrier (16 blocks) ----------------
        __syncthreads();
        if (tid == 0) {
            __threadfence();
            atomicAdd((unsigned*)bar, 1u);
            const unsigned tgt = (unsigned)(t + 1) * 16u;
            while (*bar < tgt) __nanosleep(32);
        }
        __syncthreads();
    }
}

// -------------------- launch --------------------
extern "C" void kernel_launch(void* const* d_in, const int* in_sizes, int n_in,
                              void* d_out, int out_size) {
    const float* x0    = (const float*)d_in[0];
    const float* x1    = (const float*)d_in[1];
    const float* x2    = (const float*)d_in[2];
    // d_in[3] = x_lens (unused)
    const float* gum   = (const float*)d_in[4];
    const float* W0    = (const float*)d_in[5];
    const float* b0    = (const float*)d_in[6];
    const float* W1    = (const float*)d_in[7];
    const float* b1    = (const float*)d_in[8];
    const float* W_ih  = (const float*)d_in[9];
    const float* W_hh  = (const float*)d_in[10];
    const float* b_ih  = (const float*)d_in[11];
    const float* b_hh  = (const float*)d_in[12];
    const float* W_dec = (const float*)d_in[13];
    const float* b_dec = (const float*)d_in[14];
    float* out = (float*)d_out;

    init_kernel<<<(2 * 8 * 8 * 1024 * 4 + 255) / 256, 256>>>();
    wsplitF_kernel<<<(16 * 12 * 1024 + 255) / 256, 256>>>(W_ih, W_hh);

    size_t smem1 = (size_t)(40 * 300 + 40 * 76) * sizeof(float);
    cudaFuncSetAttribute(phase1_kernel,
                         cudaFuncAttributeMaxDynamicSharedMemorySize, (int)smem1);
    phase1_kernel<<<NROWS / 32, 320, smem1>>>(x0, x1, x2, W0, b0, W1, b1);

    redsplitF_kernel<<<(S_LEN * 8 * 3 * 1024 + 255) / 256, 256>>>();

    size_t smemP = (size_t)SMEM_F * sizeof(float);   // 183552 B
    cudaFuncSetAttribute(persist_kernel,
                         cudaFuncAttributeMaxDynamicSharedMemorySize, (int)smemP);
    persist_kernel<<<NBLK, THR, smemP>>>(W_ih, W_hh, b_ih, b_hh,
                                         W_dec, b_dec, gum, out);
}